// round 16
// baseline (speedup 1.0000x reference)
#include <cuda_runtime.h>
#include <stdint.h>

#define B_  4
#define T_  128
#define C_  512
#define NH_ 8
#define HS_ 64
#define BTC (B_*T_*C_)
#define SCALE_ 0.125f
#define LOG2E_ 1.4426950408889634f
#define IT_ 8    // i's per attn block (stride 16)

// Scratch (allocation-free rule: __device__ globals)
__device__ float g_P[3 * BTC];      // p0,p1,p2 in (B,T,C) layout
__device__ float g_V[2 * BTC];      // V0,V1 in (B,T,C) layout
__device__ float g_s2[B_ * NH_ * T_];
__device__ float g_y[BTC];          // (B,T,C) layout

// ---------------------------------------------------------------------------
// helpers
// ---------------------------------------------------------------------------
__device__ __forceinline__ unsigned long long pack2(float lo, float hi)
{
    unsigned long long r;
    asm("mov.b64 %0, {%1, %2};" : "=l"(r) : "f"(lo), "f"(hi));
    return r;
}
__device__ __forceinline__ unsigned long long fma2_(unsigned long long a,
                                                    unsigned long long b,
                                                    unsigned long long c)
{
    unsigned long long d;
    asm("fma.rn.f32x2 %0, %1, %2, %3;" : "=l"(d) : "l"(a), "l"(b), "l"(c));
    return d;
}
__device__ __forceinline__ float2 unpack2(unsigned long long v)
{
    float lo, hi;
    asm("mov.b64 {%0, %1}, %2;" : "=f"(lo), "=f"(hi) : "l"(v));
    return make_float2(lo, hi);
}
__device__ __forceinline__ float ex2_(float x)
{
    float r;
    asm("ex2.approx.f32 %0, %1;" : "=f"(r) : "f"(x));
    return r;
}
__device__ __forceinline__ uint32_t tf32_(float x)
{
    uint32_t r;
    asm("cvt.rna.tf32.f32 %0, %1;" : "=r"(r) : "f"(x));
    return r;
}
__device__ __forceinline__ uint32_t smaddr(const void* p)
{
    return (uint32_t)__cvta_generic_to_shared(p);
}
#define CPA16(dst, src) \
    asm volatile("cp.async.cg.shared.global [%0], [%1], 16;" \
                 :: "r"(dst), "l"(src) : "memory")
#define CPA_COMMIT() asm volatile("cp.async.commit_group;" ::: "memory")
#define CPA_WAIT(n)  asm volatile("cp.async.wait_group %0;" :: "n"(n) : "memory")

// ---------------------------------------------------------------------------
// 4-stage cp.async pipelined fp32 GEMM: C[M,N] (+)= A[M,K] @ B[K,N].
// ---------------------------------------------------------------------------
#define BNg 64
#define BKg 16
#define STG_ 4

#define GEMM_RAW_TM4 32768
#define GEMM_RAW_TM2 24576

template<int TM, bool ROWSUM, bool ATOMIC>
__device__ __forceinline__ void gemm_body_t(
    char* raw,
    const float* __restrict__ A, const float* __restrict__ Bm,
    float* __restrict__ Cm, int M, int N, int K, int lda, int ldc,
    int kbeg, int kend)
{
    constexpr int BM = 16 * TM;
    constexpr int ABYTES = STG_ * BM * BKg * 4;
    float (*As)[BM][BKg] = (float(*)[BM][BKg])raw;
    float (*Bs)[BKg][BNg] = (float(*)[BKg][BNg])(raw + ABYTES);

    const int tid = threadIdx.x;
    const int tx = tid & 15;
    const int ty = tid >> 4;
    const int row0 = blockIdx.y * BM;
    const int col0 = blockIdx.x * BNg;

    const int a_row = tid >> 2;
    const int a_k4 = (tid & 3) << 2;
    const int b_k = tid >> 4;
    const int b_n4 = (tid & 15) << 2;
    const bool do_a = (TM == 4) || (tid < BM * 4);

    const int nt = (kend - kbeg) / BKg;

    unsigned long long acc2[TM][2];
#pragma unroll
    for (int r = 0; r < TM; r++) { acc2[r][0] = 0ull; acc2[r][1] = 0ull; }

#pragma unroll
    for (int t = 0; t < STG_ - 1; t++) {
        if (t < nt) {
            const int k0 = kbeg + t * BKg;
            if (do_a)
                CPA16(smaddr(&As[t][a_row][a_k4]),
                      &A[(size_t)(row0 + a_row) * lda + k0 + a_k4]);
            CPA16(smaddr(&Bs[t][b_k][b_n4]),
                  &Bm[(size_t)(k0 + b_k) * N + col0 + b_n4]);
        }
        CPA_COMMIT();
    }

    for (int t = 0; t < nt; t++) {
        CPA_WAIT(STG_ - 2);
        __syncthreads();
        const int st = t & (STG_ - 1);

#pragma unroll
        for (int kk = 0; kk < BKg; kk++) {
            ulonglong2 b2 = *(const ulonglong2*)&Bs[st][kk][tx * 4];
#pragma unroll
            for (int r = 0; r < TM; r++) {
                float a = As[st][ty * TM + r][kk];
                unsigned long long ap = pack2(a, a);
                acc2[r][0] = fma2_(ap, b2.x, acc2[r][0]);
                acc2[r][1] = fma2_(ap, b2.y, acc2[r][1]);
            }
        }

        const int tf = t + STG_ - 1;
        if (tf < nt) {
            const int sf = tf & (STG_ - 1);
            const int k0 = kbeg + tf * BKg;
            if (do_a)
                CPA16(smaddr(&As[sf][a_row][a_k4]),
                      &A[(size_t)(row0 + a_row) * lda + k0 + a_k4]);
            CPA16(smaddr(&Bs[sf][b_k][b_n4]),
                  &Bm[(size_t)(k0 + b_k) * N + col0 + b_n4]);
        }
        CPA_COMMIT();
    }

#pragma unroll
    for (int r = 0; r < TM; r++) {
        float2 e0 = unpack2(acc2[r][0]);
        float2 e1 = unpack2(acc2[r][1]);
        float* crow = &Cm[(size_t)(row0 + ty * TM + r) * ldc + col0 + tx * 4];
        if (ATOMIC) {
            atomicAdd(crow + 0, e0.x);
            atomicAdd(crow + 1, e0.y);
            atomicAdd(crow + 2, e1.x);
            atomicAdd(crow + 3, e1.y);
        } else {
            *(float4*)crow = make_float4(e0.x, e0.y, e1.x, e1.y);
        }
    }

    if (ROWSUM) {
        float* s_rs = (float*)raw;
        __syncthreads();
#pragma unroll
        for (int r = 0; r < TM; r++) {
            float2 e0 = unpack2(acc2[r][0]);
            float2 e1 = unpack2(acc2[r][1]);
            s_rs[(ty * TM + r) * 16 + tx] = (e0.x + e0.y) + (e1.x + e1.y);
        }
        __syncthreads();
        if (tid < BM) {
            float s = 0.f;
#pragma unroll
            for (int c = 0; c < 16; c++) s += s_rs[tid * 16 + c];
            const int grow = row0 + tid;
            const int bb = grow / T_, tt = grow % T_;
            g_s2[(bb * NH_ + blockIdx.x) * T_ + tt] = s;
        }
    }
}

__global__ void proj_kernel(const float* __restrict__ x,
                            const float* __restrict__ W0,
                            const float* __restrict__ W1,
                            const float* __restrict__ W2)
{
    __shared__ __align__(16) char raw[GEMM_RAW_TM4];
    const int z = blockIdx.z;
    if (z == 2) {
        gemm_body_t<4, true, false>(raw, x, W2, g_P + (size_t)2 * BTC,
                                    B_ * T_, C_, C_, C_, C_, 0, C_);
    } else {
        const float* W = (z == 0) ? W0 : W1;
        gemm_body_t<4, false, false>(raw, x, W, g_P + (size_t)z * BTC,
                                     B_ * T_, C_, C_, C_, C_, 0, C_);
    }
}

__global__ void vproj_kernel(const float* __restrict__ Wv0,
                             const float* __restrict__ Wv1)
{
    __shared__ __align__(16) char raw[GEMM_RAW_TM2];
    const int z = blockIdx.z;
    gemm_body_t<2, false, false>(raw, g_P + (size_t)(z + 1) * BTC,
                                 z ? Wv1 : Wv0, g_V + (size_t)z * BTC,
                                 B_ * T_ * NH_, HS_, HS_, HS_, HS_, 0, HS_);
}

// zero d_out for out_kernel's split-K atomics (and place attn at launch
// index 3, where ncu's capture window lands).
__global__ void zero_kernel(float* __restrict__ dout)
{
    ((float2*)dout)[blockIdx.x * 256 + threadIdx.x] = make_float2(0.f, 0.f);
}

__global__ void out_kernel(const float* __restrict__ Wc, float* __restrict__ out)
{
    __shared__ __align__(16) char raw[GEMM_RAW_TM2];
    const int kb = blockIdx.z * (C_ / 2);
    gemm_body_t<2, false, true>(raw, g_y, Wc, out, B_ * T_, C_, C_, C_, C_,
                                kb, kb + C_ / 2);
}

// ---------------------------------------------------------------------------
// Higher-order attention via tf32 mma.sync, i-batched, LPT-scheduled,
// diagonal-peeled. A-fragments feed raw fp32 bits to HMMA.tf32 (HW
// truncates mantissa) — removes the cvt stage from the dependency chain.
// ---------------------------------------------------------------------------
__constant__ unsigned char c_units[8][5] = {
    {0x77, 0x22, 0x32, 0x30, 0x40},
    {0x66, 0x73, 0x42, 0x20, 0x50},
    {0x76, 0x63, 0x52, 0x10, 0x60},
    {0x55, 0x53, 0x62, 0x00, 0x70},
    {0x65, 0x43, 0x72, 0x71, 0xFF},
    {0x75, 0x33, 0x11, 0x61, 0xFF},
    {0x44, 0x74, 0x21, 0x51, 0xFF},
    {0x54, 0x64, 0x31, 0x41, 0xFF},
};

#define V1P 72   // padded smem stride (conflict-free B-frag LDS)

#define MMA_TF32(d, a0, a1, a2, a3, b0, b1)                              \
    asm volatile(                                                        \
        "mma.sync.aligned.m16n8k8.row.col.f32.tf32.tf32.f32 "            \
        "{%0,%1,%2,%3}, {%4,%5,%6,%7}, {%8,%9}, {%0,%1,%2,%3};"          \
        : "+f"((d)[0]), "+f"((d)[1]), "+f"((d)[2]), "+f"((d)[3])         \
        : "r"(a0), "r"(a1), "r"(a2), "r"(a3), "r"(b0), "r"(b1))

#define MMA_KTILE(dacc, au0, au1, au2, au3, b0row, b1row)                \
    _Pragma("unroll")                                                    \
    for (int nt = 0; nt < 8; nt++) {                                     \
        uint32_t bu0 = __float_as_uint((b0row)[nt << 3]);                \
        uint32_t bu1 = __float_as_uint((b1row)[nt << 3]);                \
        MMA_TF32((dacc)[nt], au0, au1, au2, au3, bu0, bu1);              \
    }

__global__ __launch_bounds__(256, 4) void attn_kernel()
{
    const int it = blockIdx.x;           // 0..15 (i residue)
    const int h = blockIdx.y;
    const int b = blockIdx.z;
    const int tid = threadIdx.x;
    const int lane = tid & 31;
    const int warp = tid >> 5;

    __shared__ float s_v1[T_][V1P];
    __shared__ float s_a[IT_][T_];
    __shared__ float s_p0[IT_][HS_];
    __shared__ float s_y[IT_][HS_];
    __shared__ float s_pmax[T_];
    __shared__ float s_pmin[T_];
    __shared__ float s_s2[T_];
    __shared__ float s_m[IT_];
    __shared__ float s_z[IT_];

    const size_t headoff = (size_t)(b * T_) * C_ + (size_t)h * HS_;
    const float* p1 = g_P + BTC + headoff;
    const float* v0g = g_V + headoff;
    const float* v1g = g_V + BTC + headoff;
    const float* s2r = g_s2 + (b * NH_ + h) * T_;

    // ---- prologue loads (once per 8 i's) ----
    if (tid < 128) s_s2[tid] = s2r[tid];
    for (int idx = tid; idx < IT_ * HS_; idx += 256) {
        const int l = idx >> 6, d = idx & 63;
        const int i = it + (l << 4);
        s_p0[l][d] = __ldg(&g_P[headoff + (size_t)i * C_ + d]);
    }
    ((float*)s_y)[tid] = 0.f;
    ((float*)s_y)[tid + 256] = 0.f;
    if (tid < IT_) s_z[tid] = 0.f;
    for (int idx = tid; idx < T_ * 16; idx += 256) {
        const int k = idx >> 4;
        const int d4 = (idx & 15) << 2;
        float4 v = __ldg((const float4*)&v1g[(size_t)k * C_ + d4]);
        v.x = __uint_as_float(tf32_(v.x));
        v.y = __uint_as_float(tf32_(v.y));
        v.z = __uint_as_float(tf32_(v.z));
        v.w = __uint_as_float(tf32_(v.w));
        *(float4*)&s_v1[k][d4] = v;
    }
    __syncthreads();

    // ---- a2[l][j] = SCALE*log2e * p0[i_l].p1[j] ----
    {
        const int j = tid & 127;
        const int half = tid >> 7;
        const float* r = p1 + (size_t)j * C_;
        float dot0 = 0.f, dot1 = 0.f, dot2 = 0.f, dot3 = 0.f;
#pragma unroll
        for (int d = 0; d < 64; d += 4) {
            float4 rv = __ldg((const float4*)(r + d));
            float4 p0a = *(const float4*)&s_p0[half + 0][d];
            float4 p0b = *(const float4*)&s_p0[half + 2][d];
            float4 p0c = *(const float4*)&s_p0[half + 4][d];
            float4 p0d = *(const float4*)&s_p0[half + 6][d];
            dot0 = fmaf(p0a.x, rv.x, dot0); dot0 = fmaf(p0a.y, rv.y, dot0);
            dot0 = fmaf(p0a.z, rv.z, dot0); dot0 = fmaf(p0a.w, rv.w, dot0);
            dot1 = fmaf(p0b.x, rv.x, dot1); dot1 = fmaf(p0b.y, rv.y, dot1);
            dot1 = fmaf(p0b.z, rv.z, dot1); dot1 = fmaf(p0b.w, rv.w, dot1);
            dot2 = fmaf(p0c.x, rv.x, dot2); dot2 = fmaf(p0c.y, rv.y, dot2);
            dot2 = fmaf(p0c.z, rv.z, dot2); dot2 = fmaf(p0c.w, rv.w, dot2);
            dot3 = fmaf(p0d.x, rv.x, dot3); dot3 = fmaf(p0d.y, rv.y, dot3);
            dot3 = fmaf(p0d.z, rv.z, dot3); dot3 = fmaf(p0d.w, rv.w, dot3);
        }
        s_a[half + 0][j] = dot0 * (SCALE_ * LOG2E_);
        s_a[half + 2][j] = dot1 * (SCALE_ * LOG2E_);
        s_a[half + 4][j] = dot2 * (SCALE_ * LOG2E_);
        s_a[half + 6][j] = dot3 * (SCALE_ * LOG2E_);
    }
    __syncthreads();

    // ---- prefix max/min of s2 (warp 0, shuffle scan) ----
    if (warp == 0) {
        float4 s4 = *(const float4*)&s_s2[lane << 2];
        float px1 = fmaxf(s4.x, s4.y), px2 = fmaxf(px1, s4.z), px3 = fmaxf(px2, s4.w);
        float pn1 = fminf(s4.x, s4.y), pn2 = fminf(pn1, s4.z), pn3 = fminf(pn2, s4.w);
        float im = px3, in_ = pn3;
#pragma unroll
        for (int off = 1; off < 32; off <<= 1) {
            float tm = __shfl_up_sync(0xffffffffu, im, off);
            float tn = __shfl_up_sync(0xffffffffu, in_, off);
            if (lane >= off) { im = fmaxf(im, tm); in_ = fminf(in_, tn); }
        }
        float em = __shfl_up_sync(0xffffffffu, im, 1);
        float en = __shfl_up_sync(0xffffffffu, in_, 1);
        if (lane == 0) { em = -3.4e38f; en = 3.4e38f; }
        s_pmax[(lane << 2) + 0] = fmaxf(em, s4.x);
        s_pmax[(lane << 2) + 1] = fmaxf(em, px1);
        s_pmax[(lane << 2) + 2] = fmaxf(em, px2);
        s_pmax[(lane << 2) + 3] = fmaxf(em, px3);
        s_pmin[(lane << 2) + 0] = fminf(en, s4.x);
        s_pmin[(lane << 2) + 1] = fminf(en, pn1);
        s_pmin[(lane << 2) + 2] = fminf(en, pn2);
        s_pmin[(lane << 2) + 3] = fminf(en, pn3);
    }
    __syncthreads();

    // ---- exact max per i (warp l handles i_l) ----
    {
        const int i = it + (warp << 4);
        float m = -3.4e38f;
        for (int jj = lane; jj <= i; jj += 32) {
            float aj = s_a[warp][jj];
            float c = (aj >= 0.f) ? aj * s_pmax[jj] : aj * s_pmin[jj];
            m = fmaxf(m, c);
        }
#pragma unroll
        for (int o = 16; o; o >>= 1)
            m = fmaxf(m, __shfl_down_sync(0xffffffffu, m, o));
        if (lane == 0) s_m[warp] = m;
    }
    __syncthreads();

    // ---- mainloop over statically-scheduled (l, strip) units ----
    const int g = lane >> 2;
    const int t4 = lane & 3;

    for (int u = 0; u < 5; u++) {
        const unsigned int code = c_units[warp][u];
        if (code == 0xFFu) break;
        const int l = (int)(code >> 4);
        const int w = (int)(code & 15);
        const int i = it + (l << 4);
        const int jr0 = (w << 4) + g;
        const int jr1 = jr0 + 8;

        const float negm2 = -s_m[l];
        const float a0s = s_a[l][jr0];
        const float a1s = s_a[l][jr1];

        float dacc[8][4];
#pragma unroll
        for (int nt = 0; nt < 8; nt++)
#pragma unroll
            for (int e = 0; e < 4; e++) dacc[nt][e] = 0.f;
        float zp = 0.f;

        if (w < l) {
            for (int kt = 0; kt < (w << 1); kt++) {
                const int kc0 = (kt << 3) + t4;
                const int kc1 = kc0 + 4;
                float e00 = ex2_(fmaf(a0s, s_s2[kc0], negm2));
                float e10 = ex2_(fmaf(a1s, s_s2[kc0], negm2));
                float e01 = ex2_(fmaf(a0s, s_s2[kc1], negm2));
                float e11 = ex2_(fmaf(a1s, s_s2[kc1], negm2));
                zp += (e00 + e10) + (e01 + e11);
                MMA_KTILE(dacc, __float_as_uint(e00), __float_as_uint(e10),
                          __float_as_uint(e01), __float_as_uint(e11),
                          &s_v1[kc0][g], &s_v1[kc1][g]);
            }
#pragma unroll
            for (int dt = 0; dt < 2; dt++) {
                const int kt = (w << 1) + dt;
                const int kc0 = (kt << 3) + t4;
                const int kc1 = kc0 + 4;
                float e00 = ex2_(fmaf(a0s, s_s2[kc0], negm2));
                float e10 = ex2_(fmaf(a1s, s_s2[kc0], negm2));
                float e01 = ex2_(fmaf(a0s, s_s2[kc1], negm2));
                float e11 = ex2_(fmaf(a1s, s_s2[kc1], negm2));
                float w00 = (kc0 <= jr0) ? e00 : 0.f;
                float w10 = (kc0 <= jr1) ? e10 : 0.f;
                float w01 = (kc1 <= jr0) ? e01 : 0.f;
                float w11 = (kc1 <= jr1) ? e11 : 0.f;
                zp += (w00 + w10) + (w01 + w11);
                MMA_KTILE(dacc, __float_as_uint(w00), __float_as_uint(w10),
                          __float_as_uint(w01), __float_as_uint(w11),
                          &s_v1[kc0][g], &s_v1[kc1][g]);
            }
        } else {
            const bool rok0 = (jr0 <= i);
            const bool rok1 = (jr1 <= i);
            const int ktn = (i >> 3) + 1;
            for (int kt = 0; kt < ktn; kt++) {
                const int kc0 = (kt << 3) + t4;
                const int kc1 = kc0 + 4;
                float e00 = ex2_(fmaf(a0s, s_s2[kc0], negm2));
                float e10 = ex2_(fmaf(a1s, s_s2[kc0], negm2));
                float e01 = ex2_(fmaf(a0s, s_s2[kc1], negm2));
                float e11 = ex2_(fmaf(a1s, s_s2[kc1], negm2));
                float w00 = (rok0 && kc0 <= jr0) ? e00 : 0.f;
                float w10 = (rok1 && kc0 <= jr1) ? e10 : 0.f;
                float w01 = (rok0 && kc1 <= jr0) ? e01 : 0.f;
                float w11 = (rok1 && kc1 <= jr1) ? e11 : 0.f;
                zp += (w00 + w10) + (w01 + w11);
                MMA_KTILE(dacc, __float_as_uint(w00), __float_as_uint(w10),
                          __float_as_uint(w01), __float_as_uint(w11),
                          &s_v1[kc0][g], &s_v1[kc1][g]);
            }
        }

        // epilogue for this unit: y contribution (atomic into s_y)
#pragma unroll
        for (int nt = 0; nt < 8; nt++) {
            const int c0 = (nt << 3) + (t4 << 1);
            float2 va = *(const float2*)&v0g[(size_t)jr0 * C_ + c0];
            float2 vb = *(const float2*)&v0g[(size_t)jr1 * C_ + c0];
            float pc0 = fmaf(dacc[nt][0], va.x, dacc[nt][2] * vb.x);
            float pc1 = fmaf(dacc[nt][1], va.y, dacc[nt][3] * vb.y);
            pc0 += __shfl_down_sync(0xffffffffu, pc0, 16);
            pc1 += __shfl_down_sync(0xffffffffu, pc1, 16);
            pc0 += __shfl_down_sync(0xffffffffu, pc0, 8);
            pc1 += __shfl_down_sync(0xffffffffu, pc1, 8);
            pc0 += __shfl_down_sync(0xffffffffu, pc0, 4);
            pc1 += __shfl_down_sync(0xffffffffu, pc1, 4);
            if (lane < 4) {
                atomicAdd(&s_y[l][c0], pc0);
                atomicAdd(&s_y[l][c0 + 1], pc1);
            }
        }
#pragma unroll
        for (int o = 16; o; o >>= 1)
            zp += __shfl_down_sync(0xffffffffu, zp, o);
        if (lane == 0) atomicAdd(&s_z[l], zp);
    }

    __syncthreads();

    // ---- finalize ----
    for (int idx = tid; idx < IT_ * HS_; idx += 256) {
        const int l = idx >> 6, d = idx & 63;
        const int i = it + (l << 4);
        g_y[(size_t)(b * T_ + i) * C_ + (size_t)h * HS_ + d] = s_y[l][d] / s_z[l];
    }
}

// ---------------------------------------------------------------------------
extern "C" void kernel_launch(void* const* d_in, const int* in_sizes, int n_in,
                              void* d_out, int out_size)
{
    (void)in_sizes; (void)n_in; (void)out_size;
    const float* x   = (const float*)d_in[0];
    const float* Wp0 = (const float*)d_in[1];
    const float* Wp1 = (const float*)d_in[2];
    const float* Wp2 = (const float*)d_in[3];
    const float* Wv0 = (const float*)d_in[4];
    const float* Wv1 = (const float*)d_in[5];
    const float* Wc  = (const float*)d_in[6];
    float* out = (float*)d_out;

    proj_kernel<<<dim3(C_ / BNg, (B_ * T_) / 64, 3), 256>>>(x, Wp0, Wp1, Wp2);
    vproj_kernel<<<dim3(1, (B_ * T_ * NH_) / 32, 2), 256>>>(Wv0, Wv1);
    zero_kernel<<<BTC / 512, 256>>>(out);
    attn_kernel<<<dim3(T_ / IT_, NH_, B_), 256>>>();
    out_kernel<<<dim3(C_ / BNg, (B_ * T_) / 32, 2), 256>>>(Wc, out);
}

// round 17
// speedup vs baseline: 1.0450x; 1.0450x over previous
#include <cuda_runtime.h>
#include <cuda_fp16.h>
#include <stdint.h>

#define B_  4
#define T_  128
#define C_  512
#define NH_ 8
#define HS_ 64
#define BTC (B_*T_*C_)
#define SCALE_ 0.125f
#define LOG2E_ 1.4426950408889634f
#define IT_ 8    // i's per attn block (stride 16)

// Scratch (allocation-free rule: __device__ globals)
__device__ float g_P[3 * BTC];      // p0,p1,p2 in (B,T,C) layout
__device__ float g_V[2 * BTC];      // V0,V1 in (B,T,C) layout
__device__ float g_s2[B_ * NH_ * T_];
__device__ float g_y[BTC];          // (B,T,C) layout

// ---------------------------------------------------------------------------
// helpers
// ---------------------------------------------------------------------------
__device__ __forceinline__ unsigned long long pack2(float lo, float hi)
{
    unsigned long long r;
    asm("mov.b64 %0, {%1, %2};" : "=l"(r) : "f"(lo), "f"(hi));
    return r;
}
__device__ __forceinline__ unsigned long long fma2_(unsigned long long a,
                                                    unsigned long long b,
                                                    unsigned long long c)
{
    unsigned long long d;
    asm("fma.rn.f32x2 %0, %1, %2, %3;" : "=l"(d) : "l"(a), "l"(b), "l"(c));
    return d;
}
__device__ __forceinline__ float2 unpack2(unsigned long long v)
{
    float lo, hi;
    asm("mov.b64 {%0, %1}, %2;" : "=f"(lo), "=f"(hi) : "l"(v));
    return make_float2(lo, hi);
}
__device__ __forceinline__ float ex2_(float x)
{
    float r;
    asm("ex2.approx.f32 %0, %1;" : "=f"(r) : "f"(x));
    return r;
}
__device__ __forceinline__ uint32_t tf32_(float x)
{
    uint32_t r;
    asm("cvt.rna.tf32.f32 %0, %1;" : "=r"(r) : "f"(x));
    return r;
}
__device__ __forceinline__ uint32_t smaddr(const void* p)
{
    return (uint32_t)__cvta_generic_to_shared(p);
}
#define CPA16(dst, src) \
    asm volatile("cp.async.cg.shared.global [%0], [%1], 16;" \
                 :: "r"(dst), "l"(src) : "memory")
#define CPA_COMMIT() asm volatile("cp.async.commit_group;" ::: "memory")
#define CPA_WAIT(n)  asm volatile("cp.async.wait_group %0;" :: "n"(n) : "memory")

// ---------------------------------------------------------------------------
// 4-stage cp.async pipelined fp32 GEMM (unchanged, measured-best config)
// ---------------------------------------------------------------------------
#define BNg 64
#define BKg 16
#define STG_ 4

#define GEMM_RAW_TM4 32768
#define GEMM_RAW_TM2 24576

template<int TM, bool ROWSUM, bool ATOMIC>
__device__ __forceinline__ void gemm_body_t(
    char* raw,
    const float* __restrict__ A, const float* __restrict__ Bm,
    float* __restrict__ Cm, int M, int N, int K, int lda, int ldc,
    int kbeg, int kend)
{
    constexpr int BM = 16 * TM;
    constexpr int ABYTES = STG_ * BM * BKg * 4;
    float (*As)[BM][BKg] = (float(*)[BM][BKg])raw;
    float (*Bs)[BKg][BNg] = (float(*)[BKg][BNg])(raw + ABYTES);

    const int tid = threadIdx.x;
    const int tx = tid & 15;
    const int ty = tid >> 4;
    const int row0 = blockIdx.y * BM;
    const int col0 = blockIdx.x * BNg;

    const int a_row = tid >> 2;
    const int a_k4 = (tid & 3) << 2;
    const int b_k = tid >> 4;
    const int b_n4 = (tid & 15) << 2;
    const bool do_a = (TM == 4) || (tid < BM * 4);

    const int nt = (kend - kbeg) / BKg;

    unsigned long long acc2[TM][2];
#pragma unroll
    for (int r = 0; r < TM; r++) { acc2[r][0] = 0ull; acc2[r][1] = 0ull; }

#pragma unroll
    for (int t = 0; t < STG_ - 1; t++) {
        if (t < nt) {
            const int k0 = kbeg + t * BKg;
            if (do_a)
                CPA16(smaddr(&As[t][a_row][a_k4]),
                      &A[(size_t)(row0 + a_row) * lda + k0 + a_k4]);
            CPA16(smaddr(&Bs[t][b_k][b_n4]),
                  &Bm[(size_t)(k0 + b_k) * N + col0 + b_n4]);
        }
        CPA_COMMIT();
    }

    for (int t = 0; t < nt; t++) {
        CPA_WAIT(STG_ - 2);
        __syncthreads();
        const int st = t & (STG_ - 1);

#pragma unroll
        for (int kk = 0; kk < BKg; kk++) {
            ulonglong2 b2 = *(const ulonglong2*)&Bs[st][kk][tx * 4];
#pragma unroll
            for (int r = 0; r < TM; r++) {
                float a = As[st][ty * TM + r][kk];
                unsigned long long ap = pack2(a, a);
                acc2[r][0] = fma2_(ap, b2.x, acc2[r][0]);
                acc2[r][1] = fma2_(ap, b2.y, acc2[r][1]);
            }
        }

        const int tf = t + STG_ - 1;
        if (tf < nt) {
            const int sf = tf & (STG_ - 1);
            const int k0 = kbeg + tf * BKg;
            if (do_a)
                CPA16(smaddr(&As[sf][a_row][a_k4]),
                      &A[(size_t)(row0 + a_row) * lda + k0 + a_k4]);
            CPA16(smaddr(&Bs[sf][b_k][b_n4]),
                  &Bm[(size_t)(k0 + b_k) * N + col0 + b_n4]);
        }
        CPA_COMMIT();
    }

#pragma unroll
    for (int r = 0; r < TM; r++) {
        float2 e0 = unpack2(acc2[r][0]);
        float2 e1 = unpack2(acc2[r][1]);
        float* crow = &Cm[(size_t)(row0 + ty * TM + r) * ldc + col0 + tx * 4];
        if (ATOMIC) {
            atomicAdd(crow + 0, e0.x);
            atomicAdd(crow + 1, e0.y);
            atomicAdd(crow + 2, e1.x);
            atomicAdd(crow + 3, e1.y);
        } else {
            *(float4*)crow = make_float4(e0.x, e0.y, e1.x, e1.y);
        }
    }

    if (ROWSUM) {
        float* s_rs = (float*)raw;
        __syncthreads();
#pragma unroll
        for (int r = 0; r < TM; r++) {
            float2 e0 = unpack2(acc2[r][0]);
            float2 e1 = unpack2(acc2[r][1]);
            s_rs[(ty * TM + r) * 16 + tx] = (e0.x + e0.y) + (e1.x + e1.y);
        }
        __syncthreads();
        if (tid < BM) {
            float s = 0.f;
#pragma unroll
            for (int c = 0; c < 16; c++) s += s_rs[tid * 16 + c];
            const int grow = row0 + tid;
            const int bb = grow / T_, tt = grow % T_;
            g_s2[(bb * NH_ + blockIdx.x) * T_ + tt] = s;
        }
    }
}

__global__ void proj_kernel(const float* __restrict__ x,
                            const float* __restrict__ W0,
                            const float* __restrict__ W1,
                            const float* __restrict__ W2)
{
    __shared__ __align__(16) char raw[GEMM_RAW_TM4];
    const int z = blockIdx.z;
    if (z == 2) {
        gemm_body_t<4, true, false>(raw, x, W2, g_P + (size_t)2 * BTC,
                                    B_ * T_, C_, C_, C_, C_, 0, C_);
    } else {
        const float* W = (z == 0) ? W0 : W1;
        gemm_body_t<4, false, false>(raw, x, W, g_P + (size_t)z * BTC,
                                     B_ * T_, C_, C_, C_, C_, 0, C_);
    }
}

__global__ void vproj_kernel(const float* __restrict__ Wv0,
                             const float* __restrict__ Wv1)
{
    __shared__ __align__(16) char raw[GEMM_RAW_TM2];
    const int z = blockIdx.z;
    gemm_body_t<2, false, false>(raw, g_P + (size_t)(z + 1) * BTC,
                                 z ? Wv1 : Wv0, g_V + (size_t)z * BTC,
                                 B_ * T_ * NH_, HS_, HS_, HS_, HS_, 0, HS_);
}

// zero d_out for split-K out (and keep attn at ncu's captured launch index 3)
__global__ void zero_kernel(float* __restrict__ dout)
{
    ((float2*)dout)[blockIdx.x * 256 + threadIdx.x] = make_float2(0.f, 0.f);
}

__global__ void out_kernel(const float* __restrict__ Wc, float* __restrict__ out)
{
    __shared__ __align__(16) char raw[GEMM_RAW_TM2];
    const int kb = blockIdx.z * (C_ / 2);
    gemm_body_t<2, false, true>(raw, g_y, Wc, out, B_ * T_, C_, C_, C_, C_,
                                kb, kb + C_ / 2);
}

// ---------------------------------------------------------------------------
// Higher-order attention. R17 changes:
//  - V0 staged ONCE into smem as fp16 (transposed, padded) — epilogue reads
//    LDS instead of 16 dependent LDG.64/unit (the exposed-L2-latency sink).
//  - V1 stored in paired XOR-swizzled layout s_v1q: one conflict-free
//    LDS.128 supplies B-frags for TWO MMAs (16 LDS.32 -> 4 LDS.128/k-tile).
//  - dynamic smem (57280 B), phase-aliased p0/pmax/pmin with s_y; 4 CTA/SM.
// ---------------------------------------------------------------------------
__constant__ unsigned char c_units[8][5] = {
    {0x77, 0x22, 0x32, 0x30, 0x40},
    {0x66, 0x73, 0x42, 0x20, 0x50},
    {0x76, 0x63, 0x52, 0x10, 0x60},
    {0x55, 0x53, 0x62, 0x00, 0x70},
    {0x65, 0x43, 0x72, 0x71, 0xFF},
    {0x75, 0x33, 0x11, 0x61, 0xFF},
    {0x44, 0x74, 0x21, 0x51, 0xFF},
    {0x54, 0x64, 0x31, 0x41, 0xFF},
};

#define ATTN_SMEM 57280
#define V0P 131   // s_v0t row pad (half2 units)

#define MMA_TF32(d, a0, a1, a2, a3, b0, b1)                              \
    asm volatile(                                                        \
        "mma.sync.aligned.m16n8k8.row.col.f32.tf32.tf32.f32 "            \
        "{%0,%1,%2,%3}, {%4,%5,%6,%7}, {%8,%9}, {%0,%1,%2,%3};"          \
        : "+f"((d)[0]), "+f"((d)[1]), "+f"((d)[2]), "+f"((d)[3])         \
        : "r"(a0), "r"(a1), "r"(a2), "r"(a3), "r"(b0), "r"(b1))

// one k-tile: 4 LDS.128 supply B-frags for 8 MMAs
#define MMA_KTILE_Q(dacc, au0, au1, au2, au3, vkt)                       \
    _Pragma("unroll")                                                    \
    for (int nt2 = 0; nt2 < 4; nt2++) {                                  \
        float4 q = *(const float4*)((vkt) + (nt2 << 5));                 \
        MMA_TF32((dacc)[2*nt2],   au0, au1, au2, au3,                    \
                 __float_as_uint(q.x), __float_as_uint(q.y));            \
        MMA_TF32((dacc)[2*nt2+1], au0, au1, au2, au3,                    \
                 __float_as_uint(q.z), __float_as_uint(q.w));            \
    }

__global__ __launch_bounds__(256, 4) void attn_kernel()
{
    const int it = blockIdx.x;           // 0..15 (i residue)
    const int h = blockIdx.y;
    const int b = blockIdx.z;
    const int tid = threadIdx.x;
    const int lane = tid & 31;
    const int warp = tid >> 5;
    const int g = lane >> 2;
    const int t4 = lane & 3;
    const int gx = g ^ (t4 << 1);        // XOR slot for s_v1q

    extern __shared__ __align__(16) char dsm[];
    float*   s_v1q = (float*)dsm;                         // 32768 B
    __half2* s_v0t = (__half2*)(dsm + 32768);             // 16768 B [32][V0P]
    float (*s_a)[T_] = (float(*)[T_])(dsm + 49536);       //  4096 B
    char*    ph     = dsm + 53632;                        //  3072 B union
    float (*s_p0)[HS_] = (float(*)[HS_])ph;               //  ph1: p0
    float*   s_pmax = (float*)(ph + 2048);                //  ph1: pmax
    float*   s_pmin = (float*)(ph + 2560);                //  ph1: pmin
    float (*s_y)[HS_]  = (float(*)[HS_])ph;               //  ph2: y
    float*   s_s2 = (float*)(dsm + 56704);                //   512 B
    float*   s_m  = (float*)(dsm + 57216);                //    32 B
    float*   s_z  = (float*)(dsm + 57248);                //    32 B

    const size_t headoff = (size_t)(b * T_) * C_ + (size_t)h * HS_;
    const float* p1 = g_P + BTC + headoff;
    const float* v0g = g_V + headoff;
    const float* v1g = g_V + BTC + headoff;
    const float* s2r = g_s2 + (b * NH_ + h) * T_;

    // ---- prologue loads (once per 8 i's) ----
    if (tid < 128) s_s2[tid] = s2r[tid];
    if (tid < IT_) s_z[tid] = 0.f;
    for (int idx = tid; idx < IT_ * HS_; idx += 256) {
        const int l = idx >> 6, d = idx & 63;
        const int i = it + (l << 4);
        s_p0[l][d] = __ldg(&g_P[headoff + (size_t)i * C_ + d]);
    }
    // V0 -> fp16 smem, transposed [c2][j] (coalesced reads)
    for (int idx = tid; idx < T_ * 32; idx += 256) {
        const int c2 = idx & 31;
        const int j = idx >> 5;
        float2 v = *(const float2*)&v0g[(size_t)j * C_ + (c2 << 1)];
        s_v0t[c2 * V0P + j] = __floats2half2_rn(v.x, v.y);
    }
    // V1 -> paired XOR-swizzled layout (tf32-rounded)
    for (int Gq = tid; Gq < 2048; Gq += 256) {
        const int gg = Gq & 7;
        const int n2 = (Gq >> 3) & 3;
        const int tt = (Gq >> 5) & 3;
        const int kk = Gq >> 7;
        const int k0 = (kk << 3) + tt;
        const int d0 = (n2 << 4) + gg;
        float4 val;
        val.x = __uint_as_float(tf32_(v1g[(size_t)k0 * C_ + d0]));
        val.y = __uint_as_float(tf32_(v1g[(size_t)(k0 + 4) * C_ + d0]));
        val.z = __uint_as_float(tf32_(v1g[(size_t)k0 * C_ + d0 + 8]));
        val.w = __uint_as_float(tf32_(v1g[(size_t)(k0 + 4) * C_ + d0 + 8]));
        const int gw = gg ^ (tt << 1);
        *(float4*)&s_v1q[((((kk << 2) + tt) << 2) + n2) * 32 + (gw << 2)] = val;
    }
    __syncthreads();

    // ---- a2[l][j] = SCALE*log2e * p0[i_l].p1[j] ----
    {
        const int j = tid & 127;
        const int half = tid >> 7;
        const float* r = p1 + (size_t)j * C_;
        float dot0 = 0.f, dot1 = 0.f, dot2 = 0.f, dot3 = 0.f;
#pragma unroll
        for (int d = 0; d < 64; d += 4) {
            float4 rv = __ldg((const float4*)(r + d));
            float4 p0a = *(const float4*)&s_p0[half + 0][d];
            float4 p0b = *(const float4*)&s_p0[half + 2][d];
            float4 p0c = *(const float4*)&s_p0[half + 4][d];
            float4 p0d = *(const float4*)&s_p0[half + 6][d];
            dot0 = fmaf(p0a.x, rv.x, dot0); dot0 = fmaf(p0a.y, rv.y, dot0);
            dot0 = fmaf(p0a.z, rv.z, dot0); dot0 = fmaf(p0a.w, rv.w, dot0);
            dot1 = fmaf(p0b.x, rv.x, dot1); dot1 = fmaf(p0b.y, rv.y, dot1);
            dot1 = fmaf(p0b.z, rv.z, dot1); dot1 = fmaf(p0b.w, rv.w, dot1);
            dot2 = fmaf(p0c.x, rv.x, dot2); dot2 = fmaf(p0c.y, rv.y, dot2);
            dot2 = fmaf(p0c.z, rv.z, dot2); dot2 = fmaf(p0c.w, rv.w, dot2);
            dot3 = fmaf(p0d.x, rv.x, dot3); dot3 = fmaf(p0d.y, rv.y, dot3);
            dot3 = fmaf(p0d.z, rv.z, dot3); dot3 = fmaf(p0d.w, rv.w, dot3);
        }
        s_a[half + 0][j] = dot0 * (SCALE_ * LOG2E_);
        s_a[half + 2][j] = dot1 * (SCALE_ * LOG2E_);
        s_a[half + 4][j] = dot2 * (SCALE_ * LOG2E_);
        s_a[half + 6][j] = dot3 * (SCALE_ * LOG2E_);
    }
    __syncthreads();

    // ---- prefix max/min of s2 (warp 0, shuffle scan) ----
    if (warp == 0) {
        float4 s4 = *(const float4*)&s_s2[lane << 2];
        float px1 = fmaxf(s4.x, s4.y), px2 = fmaxf(px1, s4.z), px3 = fmaxf(px2, s4.w);
        float pn1 = fminf(s4.x, s4.y), pn2 = fminf(pn1, s4.z), pn3 = fminf(pn2, s4.w);
        float im = px3, in_ = pn3;
#pragma unroll
        for (int off = 1; off < 32; off <<= 1) {
            float tm = __shfl_up_sync(0xffffffffu, im, off);
            float tn = __shfl_up_sync(0xffffffffu, in_, off);
            if (lane >= off) { im = fmaxf(im, tm); in_ = fminf(in_, tn); }
        }
        float em = __shfl_up_sync(0xffffffffu, im, 1);
        float en = __shfl_up_sync(0xffffffffu, in_, 1);
        if (lane == 0) { em = -3.4e38f; en = 3.4e38f; }
        s_pmax[(lane << 2) + 0] = fmaxf(em, s4.x);
        s_pmax[(lane << 2) + 1] = fmaxf(em, px1);
        s_pmax[(lane << 2) + 2] = fmaxf(em, px2);
        s_pmax[(lane << 2) + 3] = fmaxf(em, px3);
        s_pmin[(lane << 2) + 0] = fminf(en, s4.x);
        s_pmin[(lane << 2) + 1] = fminf(en, pn1);
        s_pmin[(lane << 2) + 2] = fminf(en, pn2);
        s_pmin[(lane << 2) + 3] = fminf(en, pn3);
    }
    __syncthreads();

    // ---- exact max per i (warp l handles i_l) ----
    {
        const int i = it + (warp << 4);
        float m = -3.4e38f;
        for (int jj = lane; jj <= i; jj += 32) {
            float aj = s_a[warp][jj];
            float c = (aj >= 0.f) ? aj * s_pmax[jj] : aj * s_pmin[jj];
            m = fmaxf(m, c);
        }
#pragma unroll
        for (int o = 16; o; o >>= 1)
            m = fmaxf(m, __shfl_down_sync(0xffffffffu, m, o));
        if (lane == 0) s_m[warp] = m;
    }
    __syncthreads();

    // ---- zero y accumulators (aliases p0/pmax/pmin, now dead) ----
    ((float*)s_y)[tid] = 0.f;
    ((float*)s_y)[tid + 256] = 0.f;
    __syncthreads();

    // ---- mainloop over statically-scheduled (l, strip) units ----
    const float* vthr = s_v1q + (t4 << 7) + (gx << 2);

    for (int u = 0; u < 5; u++) {
        const unsigned int code = c_units[warp][u];
        if (code == 0xFFu) break;
        const int l = (int)(code >> 4);
        const int w = (int)(code & 15);
        const int i = it + (l << 4);
        const int jr0 = (w << 4) + g;
        const int jr1 = jr0 + 8;

        const float negm2 = -s_m[l];
        const float a0s = s_a[l][jr0];
        const float a1s = s_a[l][jr1];

        float dacc[8][4];
#pragma unroll
        for (int nt = 0; nt < 8; nt++)
#pragma unroll
            for (int e = 0; e < 4; e++) dacc[nt][e] = 0.f;
        float zp = 0.f;

        if (w < l) {
            for (int kt = 0; kt < (w << 1); kt++) {
                const int kc0 = (kt << 3) + t4;
                const int kc1 = kc0 + 4;
                float e00 = ex2_(fmaf(a0s, s_s2[kc0], negm2));
                float e10 = ex2_(fmaf(a1s, s_s2[kc0], negm2));
                float e01 = ex2_(fmaf(a0s, s_s2[kc1], negm2));
                float e11 = ex2_(fmaf(a1s, s_s2[kc1], negm2));
                zp += (e00 + e10) + (e01 + e11);
                MMA_KTILE_Q(dacc, __float_as_uint(e00), __float_as_uint(e10),
                            __float_as_uint(e01), __float_as_uint(e11),
                            vthr + (kt << 9));
            }
#pragma unroll
            for (int dt = 0; dt < 2; dt++) {
                const int kt = (w << 1) + dt;
                const int kc0 = (kt << 3) + t4;
                const int kc1 = kc0 + 4;
                float e00 = ex2_(fmaf(a0s, s_s2[kc0], negm2));
                float e10 = ex2_(fmaf(a1s, s_s2[kc0], negm2));
                float e01 = ex2_(fmaf(a0s, s_s2[kc1], negm2));
                float e11 = ex2_(fmaf(a1s, s_s2[kc1], negm2));
                float w00 = (kc0 <= jr0) ? e00 : 0.f;
                float w10 = (kc0 <= jr1) ? e10 : 0.f;
                float w01 = (kc1 <= jr0) ? e01 : 0.f;
                float w11 = (kc1 <= jr1) ? e11 : 0.f;
                zp += (w00 + w10) + (w01 + w11);
                MMA_KTILE_Q(dacc, __float_as_uint(w00), __float_as_uint(w10),
                            __float_as_uint(w01), __float_as_uint(w11),
                            vthr + (kt << 9));
            }
        } else {
            const bool rok0 = (jr0 <= i);
            const bool rok1 = (jr1 <= i);
            const int ktn = (i >> 3) + 1;
            for (int kt = 0; kt < ktn; kt++) {
                const int kc0 = (kt << 3) + t4;
                const int kc1 = kc0 + 4;
                float e00 = ex2_(fmaf(a0s, s_s2[kc0], negm2));
                float e10 = ex2_(fmaf(a1s, s_s2[kc0], negm2));
                float e01 = ex2_(fmaf(a0s, s_s2[kc1], negm2));
                float e11 = ex2_(fmaf(a1s, s_s2[kc1], negm2));
                float w00 = (rok0 && kc0 <= jr0) ? e00 : 0.f;
                float w10 = (rok1 && kc0 <= jr1) ? e10 : 0.f;
                float w01 = (rok0 && kc1 <= jr0) ? e01 : 0.f;
                float w11 = (rok1 && kc1 <= jr1) ? e11 : 0.f;
                zp += (w00 + w10) + (w01 + w11);
                MMA_KTILE_Q(dacc, __float_as_uint(w00), __float_as_uint(w10),
                            __float_as_uint(w01), __float_as_uint(w11),
                            vthr + (kt << 9));
            }
        }

        // epilogue: V0 from fp16 smem (no global loads)
#pragma unroll
        for (int nt = 0; nt < 8; nt++) {
            const int c0 = (nt << 3) + (t4 << 1);
            const int c2 = (nt << 2) + t4;
            float2 va = __half22float2(s_v0t[c2 * V0P + jr0]);
            float2 vb = __half22float2(s_v0t[c2 * V0P + jr1]);
            float pc0 = fmaf(dacc[nt][0], va.x, dacc[nt][2] * vb.x);
            float pc1 = fmaf(dacc[nt][1], va.y, dacc[nt][3] * vb.y);
            pc0 += __shfl_down_sync(0xffffffffu, pc0, 16);
            pc1 += __shfl_down_sync(0xffffffffu, pc1, 16);
            pc0 += __shfl_down_sync(0xffffffffu, pc0, 8);
            pc1 += __shfl_down_sync(0xffffffffu, pc1, 8);
            pc0 += __shfl_down_sync(0xffffffffu, pc0, 4);
            pc1 += __shfl_down_sync(0xffffffffu, pc1, 4);
            if (lane < 4) {
                atomicAdd(&s_y[l][c0], pc0);
                atomicAdd(&s_y[l][c0 + 1], pc1);
            }
        }
#pragma unroll
        for (int o = 16; o; o >>= 1)
            zp += __shfl_down_sync(0xffffffffu, zp, o);
        if (lane == 0) atomicAdd(&s_z[l], zp);
    }

    __syncthreads();

    // ---- finalize ----
    for (int idx = tid; idx < IT_ * HS_; idx += 256) {
        const int l = idx >> 6, d = idx & 63;
        const int i = it + (l << 4);
        g_y[(size_t)(b * T_ + i) * C_ + (size_t)h * HS_ + d] = s_y[l][d] / s_z[l];
    }
}

// ---------------------------------------------------------------------------
extern "C" void kernel_launch(void* const* d_in, const int* in_sizes, int n_in,
                              void* d_out, int out_size)
{
    (void)in_sizes; (void)n_in; (void)out_size;
    const float* x   = (const float*)d_in[0];
    const float* Wp0 = (const float*)d_in[1];
    const float* Wp1 = (const float*)d_in[2];
    const float* Wp2 = (const float*)d_in[3];
    const float* Wv0 = (const float*)d_in[4];
    const float* Wv1 = (const float*)d_in[5];
    const float* Wc  = (const float*)d_in[6];
    float* out = (float*)d_out;

    cudaFuncSetAttribute(attn_kernel,
                         cudaFuncAttributeMaxDynamicSharedMemorySize,
                         ATTN_SMEM);

    proj_kernel<<<dim3(C_ / BNg, (B_ * T_) / 64, 3), 256>>>(x, Wp0, Wp1, Wp2);
    vproj_kernel<<<dim3(1, (B_ * T_ * NH_) / 32, 2), 256>>>(Wv0, Wv1);
    zero_kernel<<<BTC / 512, 256>>>(out);
    attn_kernel<<<dim3(T_ / IT_, NH_, B_), 256, ATTN_SMEM>>>();
    out_kernel<<<dim3(C_ / BNg, (B_ * T_) / 32, 2), 256>>>(Wc, out);
}